// round 1
// baseline (speedup 1.0000x reference)
#include <cuda_runtime.h>
#include <math.h>

#define DMODEL 1024
#define TLEN   1024
#define BATCH  2
#define NHEAD  16
#define HS     64
#define NEXP   8
#define FFDIM  4096
#define NTOK   (BATCH*TLEN)          // 2048
#define BHTS   (BATCH*NHEAD*TLEN*HS) // 2097152
#define GROWS  (2*NTOK + 64)         // gathered rows capacity (+pad for tile overread)

// ---------------- scratch (__device__ globals; no allocs) ----------------
__device__ float g_qkv[3u*BHTS];        // q | k | v, each [B,H,T,HS]
__device__ float g_attn[BHTS];          // attention out [B,H,T,HS]
__device__ float g_y[(size_t)NTOK*DMODEL];
__device__ float g_topw[NTOK*2];
__device__ int   g_topi[NTOK*2];
__device__ int   g_rowpos[NTOK*2];
__device__ int   g_count[NEXP];
__device__ int   g_offset[NEXP];
__device__ int   g_cursor[NEXP];
__device__ float g_xg[(size_t)GROWS*DMODEL];
__device__ float g_hbuf[(size_t)GROWS*FFDIM];
__device__ float g_eo[(size_t)GROWS*DMODEL];

// ---------------- shared tiled SGEMM body: 64x64 tile, BK=16, 256 thr ----------------
__device__ __forceinline__ void gemm_body(
    const float* __restrict__ A, int lda,
    const float* __restrict__ B, int ldb,
    float* __restrict__ C, int ldc,
    int K, const float* __restrict__ bias, bool relu, int validRows)
{
    __shared__ float As[16][64];
    __shared__ float Bs[16][68];
    const int tid  = threadIdx.x;
    const int tx   = tid & 15, ty = tid >> 4;
    const int arow = tid >> 2, acol = (tid & 3) << 2;
    const int brow = tid >> 4, bcol = (tid & 15) << 2;

    float acc[4][4];
#pragma unroll
    for (int i = 0; i < 4; i++)
#pragma unroll
        for (int j = 0; j < 4; j++) acc[i][j] = 0.f;

    for (int k0 = 0; k0 < K; k0 += 16) {
        float4 av = *(const float4*)(A + (size_t)arow*lda + k0 + acol);
        float4 bv = *(const float4*)(B + (size_t)(k0+brow)*ldb + bcol);
        As[acol+0][arow] = av.x; As[acol+1][arow] = av.y;
        As[acol+2][arow] = av.z; As[acol+3][arow] = av.w;
        *(float4*)(&Bs[brow][bcol]) = bv;
        __syncthreads();
#pragma unroll
        for (int kk = 0; kk < 16; kk++) {
            float a0 = As[kk][(ty<<2)+0], a1 = As[kk][(ty<<2)+1];
            float a2 = As[kk][(ty<<2)+2], a3 = As[kk][(ty<<2)+3];
            float q0 = Bs[kk][(tx<<2)+0], q1 = Bs[kk][(tx<<2)+1];
            float q2 = Bs[kk][(tx<<2)+2], q3 = Bs[kk][(tx<<2)+3];
            acc[0][0] += a0*q0; acc[0][1] += a0*q1; acc[0][2] += a0*q2; acc[0][3] += a0*q3;
            acc[1][0] += a1*q0; acc[1][1] += a1*q1; acc[1][2] += a1*q2; acc[1][3] += a1*q3;
            acc[2][0] += a2*q0; acc[2][1] += a2*q1; acc[2][2] += a2*q2; acc[2][3] += a2*q3;
            acc[3][0] += a3*q0; acc[3][1] += a3*q1; acc[3][2] += a3*q2; acc[3][3] += a3*q3;
        }
        __syncthreads();
    }
#pragma unroll
    for (int i = 0; i < 4; i++) {
        int r = (ty<<2) + i;
        if (r < validRows) {
#pragma unroll
            for (int j = 0; j < 4; j++) {
                int c = (tx<<2) + j;
                float v = acc[i][j];
                if (bias) v += bias[c];
                if (relu) v = fmaxf(v, 0.f);
                C[(size_t)r*ldc + c] = v;
            }
        }
    }
}

// ---------------- K1: QKV projection ----------------
__global__ void k_qkv(const float* __restrict__ x,
                      const float* __restrict__ Wq,
                      const float* __restrict__ Wk,
                      const float* __restrict__ Wv)
{
    int mt = blockIdx.x, h = blockIdx.y, z = blockIdx.z;
    const float* W = (z == 0 ? Wq : (z == 1 ? Wk : Wv)) + (size_t)h*DMODEL*HS;
    int m0 = mt*64;
    int b  = m0 / TLEN;
    int t0 = m0 % TLEN;
    const float* A = x + (size_t)m0*DMODEL;
    float* C = g_qkv + (size_t)z*BHTS + ((size_t)(b*NHEAD + h)*TLEN + t0)*HS;
    gemm_body(A, DMODEL, W, HS, C, HS, DMODEL, nullptr, false, 64);
}

// ---------------- K2: causal flash attention, Br=64, Bc=32, 128 threads ----------------
__global__ void k_attn()
{
    int qt = blockIdx.x;   // query tile (64 rows)
    int bh = blockIdx.y;   // b*NHEAD + h
    const float* Q  = g_qkv + ((size_t)bh*TLEN + qt*64)*HS;
    const float* Kp = g_qkv + (size_t)BHTS   + (size_t)bh*TLEN*HS;
    const float* Vp = g_qkv + (size_t)2*BHTS + (size_t)bh*TLEN*HS;

    __shared__ float Qs[64][68];
    __shared__ float Ks[32][68];
    __shared__ float Vs[32][68];
    __shared__ float Ps[64][36];

    const int tid  = threadIdx.x;
    const int r    = tid >> 1;
    const int half = tid & 1;
    const int c0   = half * 16;   // S columns owned (16 of 32)
    const int d0   = half * 32;   // O columns owned (32 of 64)
    const float scale = 0.03125f; // 1024^-0.5

    // load Q tile
    {
        int lr = tid >> 1, lc = (tid & 1) * 32;
#pragma unroll
        for (int i = 0; i < 8; i++)
            *(float4*)&Qs[lr][lc + i*4] = *(const float4*)(Q + (size_t)lr*HS + lc + i*4);
    }

    float m_i = -1e30f, l_i = 0.f;
    float o[32];
#pragma unroll
    for (int d = 0; d < 32; d++) o[d] = 0.f;

    const int q_glob = qt*64 + r;
    const int nkt = 2*qt + 2;
    for (int kt = 0; kt < nkt; kt++) {
        __syncthreads();
        {
            int lr = tid >> 2, lc = (tid & 3) * 16;
#pragma unroll
            for (int i = 0; i < 4; i++) {
                *(float4*)&Ks[lr][lc + i*4] = *(const float4*)(Kp + ((size_t)kt*32 + lr)*HS + lc + i*4);
                *(float4*)&Vs[lr][lc + i*4] = *(const float4*)(Vp + ((size_t)kt*32 + lr)*HS + lc + i*4);
            }
        }
        __syncthreads();

        float s[16];
#pragma unroll
        for (int c = 0; c < 16; c++) s[c] = 0.f;
        for (int kk = 0; kk < 64; kk++) {
            float qv = Qs[r][kk];
#pragma unroll
            for (int c = 0; c < 16; c++) s[c] += qv * Ks[c0 + c][kk];
        }
        float mloc = -1e30f;
#pragma unroll
        for (int c = 0; c < 16; c++) {
            s[c] *= scale;
            int s_glob = kt*32 + c0 + c;
            if (s_glob > q_glob) s[c] = -1e30f;
            mloc = fmaxf(mloc, s[c]);
        }
        float mpair = fmaxf(mloc, __shfl_xor_sync(0xffffffffu, mloc, 1));
        float mnew  = fmaxf(m_i, mpair);
        float corr  = __expf(m_i - mnew);
        float lsum  = 0.f;
#pragma unroll
        for (int c = 0; c < 16; c++) {
            float p = __expf(s[c] - mnew);
            Ps[r][c0 + c] = p;
            lsum += p;
        }
        lsum += __shfl_xor_sync(0xffffffffu, lsum, 1);
        l_i = l_i * corr + lsum;
#pragma unroll
        for (int d = 0; d < 32; d++) o[d] *= corr;
        m_i = mnew;
        __syncthreads();
        for (int cc = 0; cc < 32; cc++) {
            float p = Ps[r][cc];
#pragma unroll
            for (int d = 0; d < 32; d++) o[d] += p * Vs[cc][d0 + d];
        }
    }
    float inv = 1.f / l_i;
    float* outp = g_attn + ((size_t)bh*TLEN + q_glob)*HS + d0;
#pragma unroll
    for (int d = 0; d < 32; d++) outp[d] = o[d] * inv;
}

// ---------------- block reduce helper ----------------
__device__ __forceinline__ float block_sum(float v)
{
    __shared__ float red[256];
    int tid = threadIdx.x;
    red[tid] = v;
    __syncthreads();
    for (int s = 128; s > 0; s >>= 1) {
        if (tid < s) red[tid] += red[tid + s];
        __syncthreads();
    }
    float r = red[0];
    __syncthreads();
    return r;
}

// ---------------- K3: y = x + LN(concat(attn)) ----------------
__global__ void k_ln1(const float* __restrict__ x,
                      const float* __restrict__ g, const float* __restrict__ bln)
{
    int n = blockIdx.x;
    int b = n >> 10, t = n & 1023;
    int tid = threadIdx.x;
    float v[4];
#pragma unroll
    for (int i = 0; i < 4; i++) {
        int d = tid + i*256;
        int h = d >> 6, f = d & 63;
        v[i] = g_attn[(((size_t)(b*NHEAD + h))*TLEN + t)*HS + f];
    }
    float s = v[0] + v[1] + v[2] + v[3];
    s = block_sum(s);
    float mean = s * (1.f/DMODEL);
    float q = 0.f;
#pragma unroll
    for (int i = 0; i < 4; i++) { float dd = v[i] - mean; q += dd*dd; }
    q = block_sum(q);
    float rstd = rsqrtf(q * (1.f/DMODEL) + 1e-5f);
#pragma unroll
    for (int i = 0; i < 4; i++) {
        int d = tid + i*256;
        float ln = (v[i] - mean) * rstd * g[d] + bln[d];
        g_y[(size_t)n*DMODEL + d] = x[(size_t)n*DMODEL + d] + ln;
    }
}

// ---------------- K0: zero routing state ----------------
__global__ void k_zero()
{
    int i = threadIdx.x;
    if (i < NEXP) { g_count[i] = 0; g_cursor[i] = 0; }
}

// ---------------- K4: gate logits + top-2 + softmax weights ----------------
__global__ void k_gate(const float* __restrict__ gate_W)
{
    int n = blockIdx.x*8 + (threadIdx.x >> 5);
    int lane = threadIdx.x & 31;
    const float* yr = g_y + (size_t)n*DMODEL;
    float acc[NEXP];
#pragma unroll
    for (int e = 0; e < NEXP; e++) acc[e] = 0.f;
    for (int d = lane; d < DMODEL; d += 32) {
        float yv = yr[d];
        const float* gw = gate_W + (size_t)d*NEXP;
#pragma unroll
        for (int e = 0; e < NEXP; e++) acc[e] += yv * gw[e];
    }
#pragma unroll
    for (int e = 0; e < NEXP; e++)
        for (int off = 16; off; off >>= 1)
            acc[e] += __shfl_xor_sync(0xffffffffu, acc[e], off);
    if (lane == 0) {
        float best = -1e30f; int bi = 0;
#pragma unroll
        for (int e = 0; e < NEXP; e++) if (acc[e] > best) { best = acc[e]; bi = e; }
        float best2 = -1e30f; int bi2 = 0;
#pragma unroll
        for (int e = 0; e < NEXP; e++) if (e != bi && acc[e] > best2) { best2 = acc[e]; bi2 = e; }
        float w0 = 1.f / (1.f + expf(best2 - best));
        g_topw[2*n]   = w0;  g_topw[2*n+1] = 1.f - w0;
        g_topi[2*n]   = bi;  g_topi[2*n+1] = bi2;
        atomicAdd(&g_count[bi],  1);
        atomicAdd(&g_count[bi2], 1);
    }
}

// ---------------- K5: expert offsets ----------------
__global__ void k_offs()
{
    if (threadIdx.x == 0) {
        int o = 0;
        for (int e = 0; e < NEXP; e++) { g_offset[e] = o; o += g_count[e]; }
    }
}

// ---------------- K6: assign rows + gather y into per-expert segments ----------------
__global__ void k_gather()
{
    int p = blockIdx.x;
    int n = p >> 1;
    __shared__ int spos;
    if (threadIdx.x == 0) {
        int e = g_topi[p];
        int pos = g_offset[e] + atomicAdd(&g_cursor[e], 1);
        g_rowpos[p] = pos;
        spos = pos;
    }
    __syncthreads();
    int pos = spos;
    const float4* src = (const float4*)(g_y  + (size_t)n  *DMODEL);
    float4*       dst = (float4*)      (g_xg + (size_t)pos*DMODEL);
    dst[threadIdx.x] = src[threadIdx.x];
}

// ---------------- K7: expert up-proj + relu ----------------
__global__ void k_up(const float* __restrict__ W1, const float* __restrict__ b1)
{
    int e = blockIdx.z;
    int cnt = g_count[e];
    int m0 = blockIdx.y * 64;
    if (m0 >= cnt) return;
    int base = g_offset[e] + m0;
    const float* A  = g_xg + (size_t)base*DMODEL;
    const float* Bw = W1 + (size_t)e*DMODEL*FFDIM + blockIdx.x*64;
    float* C = g_hbuf + (size_t)base*FFDIM + blockIdx.x*64;
    int vr = cnt - m0; if (vr > 64) vr = 64;
    gemm_body(A, DMODEL, Bw, FFDIM, C, FFDIM, DMODEL,
              b1 + (size_t)e*FFDIM + blockIdx.x*64, true, vr);
}

// ---------------- K8: expert down-proj ----------------
__global__ void k_down(const float* __restrict__ W2, const float* __restrict__ b2)
{
    int e = blockIdx.z;
    int cnt = g_count[e];
    int m0 = blockIdx.y * 64;
    if (m0 >= cnt) return;
    int base = g_offset[e] + m0;
    const float* A  = g_hbuf + (size_t)base*FFDIM;
    const float* Bw = W2 + (size_t)e*FFDIM*DMODEL + blockIdx.x*64;
    float* C = g_eo + (size_t)base*DMODEL + blockIdx.x*64;
    int vr = cnt - m0; if (vr > 64) vr = 64;
    gemm_body(A, FFDIM, Bw, DMODEL, C, DMODEL, FFDIM,
              b2 + (size_t)e*DMODEL + blockIdx.x*64, false, vr);
}

// ---------------- K9: combine top-2, LN2, residual ----------------
__global__ void k_out(const float* __restrict__ g, const float* __restrict__ bln,
                      float* __restrict__ out)
{
    int n = blockIdx.x;
    int tid = threadIdx.x;
    int r0 = g_rowpos[2*n], r1 = g_rowpos[2*n+1];
    float w0 = g_topw[2*n], w1 = g_topw[2*n+1];
    float v[4];
#pragma unroll
    for (int i = 0; i < 4; i++) {
        int d = tid + i*256;
        v[i] = w0 * g_eo[(size_t)r0*DMODEL + d] + w1 * g_eo[(size_t)r1*DMODEL + d];
    }
    float s = v[0] + v[1] + v[2] + v[3];
    s = block_sum(s);
    float mean = s * (1.f/DMODEL);
    float q = 0.f;
#pragma unroll
    for (int i = 0; i < 4; i++) { float dd = v[i] - mean; q += dd*dd; }
    q = block_sum(q);
    float rstd = rsqrtf(q * (1.f/DMODEL) + 1e-5f);
#pragma unroll
    for (int i = 0; i < 4; i++) {
        int d = tid + i*256;
        float ln = (v[i] - mean) * rstd * g[d] + bln[d];
        out[(size_t)n*DMODEL + d] = g_y[(size_t)n*DMODEL + d] + ln;
    }
}

// ---------------- launch ----------------
extern "C" void kernel_launch(void* const* d_in, const int* in_sizes, int n_in,
                              void* d_out, int out_size)
{
    const float* x      = (const float*)d_in[0];
    const float* Wq     = (const float*)d_in[1];
    const float* Wk     = (const float*)d_in[2];
    const float* Wv     = (const float*)d_in[3];
    const float* gate_W = (const float*)d_in[4];
    const float* W1     = (const float*)d_in[5];
    const float* b1     = (const float*)d_in[6];
    const float* W2     = (const float*)d_in[7];
    const float* b2     = (const float*)d_in[8];
    const float* ln1g   = (const float*)d_in[9];
    const float* ln1b   = (const float*)d_in[10];
    const float* ln2g   = (const float*)d_in[11];
    const float* ln2b   = (const float*)d_in[12];
    float* out = (float*)d_out;

    k_zero  <<<1, 32>>>();
    k_qkv   <<<dim3(NTOK/64, NHEAD, 3), 256>>>(x, Wq, Wk, Wv);
    k_attn  <<<dim3(TLEN/64, BATCH*NHEAD), 128>>>();
    k_ln1   <<<NTOK, 256>>>(x, ln1g, ln1b);
    k_gate  <<<NTOK/8, 256>>>(gate_W);
    k_offs  <<<1, 1>>>();
    k_gather<<<NTOK*2, 256>>>();
    k_up    <<<dim3(FFDIM/64, NTOK/64, NEXP), 256>>>(W1, b1);
    k_down  <<<dim3(DMODEL/64, NTOK/64, NEXP), 256>>>(W2, b2);
    k_out   <<<NTOK, 256>>>(ln2g, ln2b, out);
}

// round 4
// speedup vs baseline: 2.1609x; 2.1609x over previous
#include <cuda_runtime.h>
#include <cuda_bf16.h>
#include <math.h>
#include <stdint.h>

#define DMODEL 1024
#define TLEN   1024
#define BATCH  2
#define NHEAD  16
#define HS     64
#define NEXP   8
#define FFDIM  4096
#define NTOK   (BATCH*TLEN)          // 2048
#define QKVN   (3*DMODEL)            // 3072
#define GROWS  (2*NTOK + 192)        // gathered rows capacity (+pad for tile overread)

// ---------------- scratch (__device__ globals; no allocs) ----------------
__device__ float g_wqkvt[(size_t)QKVN*DMODEL];          // [3072,1024] K-major qkv weights
__device__ float g_w1t[(size_t)NEXP*FFDIM*DMODEL];      // [e][FF][D]
__device__ float g_w2t[(size_t)NEXP*DMODEL*FFDIM];      // [e][D][FF]
__device__ float g_qkvtmp[(size_t)NTOK*QKVN];           // [2048,3072]
__device__ float g_attn[(size_t)NTOK*DMODEL];           // [b,t,d] concat
__device__ float g_y[(size_t)NTOK*DMODEL];
__device__ float g_topw[NTOK*2];
__device__ int   g_topi[NTOK*2];
__device__ int   g_rowpos[NTOK*2];
__device__ int   g_count[NEXP];
__device__ int   g_offset[NEXP];
__device__ int   g_cursor[NEXP];
__device__ float g_xg[(size_t)GROWS*DMODEL];
__device__ float g_hbuf[(size_t)GROWS*FFDIM];
__device__ float g_eo[(size_t)GROWS*DMODEL];

// ================= bf16x3 split-precision mma helpers =================
__device__ __forceinline__ void mma_bf16(float d[4], const uint32_t a[4], const uint32_t b[2]) {
    asm volatile(
        "mma.sync.aligned.m16n8k16.row.col.f32.bf16.bf16.f32 "
        "{%0,%1,%2,%3}, {%4,%5,%6,%7}, {%8,%9}, {%0,%1,%2,%3};"
        : "+f"(d[0]), "+f"(d[1]), "+f"(d[2]), "+f"(d[3])
        : "r"(a[0]), "r"(a[1]), "r"(a[2]), "r"(a[3]), "r"(b[0]), "r"(b[1]));
}
// split (x,y) into packed bf16x2 hi and lo words
__device__ __forceinline__ void split2(float x, float y, uint32_t& h, uint32_t& l) {
    unsigned short hx = __bfloat16_as_ushort(__float2bfloat16_rn(x));
    unsigned short hy = __bfloat16_as_ushort(__float2bfloat16_rn(y));
    float fx = __uint_as_float(((uint32_t)hx) << 16);
    float fy = __uint_as_float(((uint32_t)hy) << 16);
    unsigned short lx = __bfloat16_as_ushort(__float2bfloat16_rn(x - fx));
    unsigned short ly = __bfloat16_as_ushort(__float2bfloat16_rn(y - fy));
    h = ((uint32_t)hy << 16) | (uint32_t)hx;
    l = ((uint32_t)ly << 16) | (uint32_t)lx;
}

// ================= bf16x3 GEMM body: 128x128 tile, Kchunk=16, 256 thr =================
#define LDW 12   // u32 words per row (8 used + 4 pad) -> conflict-free fragment reads

__device__ __forceinline__ void gemm_mma_body(
    const float* __restrict__ A, int lda,
    const float* __restrict__ B, int ldb,   // B is K-major: B[n][k]
    float* __restrict__ C, int ldc,
    int K, int Mvalid, const float* __restrict__ bias, bool relu)
{
    __shared__ uint32_t AsH[128*LDW];
    __shared__ uint32_t AsL[128*LDW];
    __shared__ uint32_t BsH[128*LDW];
    __shared__ uint32_t BsL[128*LDW];

    const int tid = threadIdx.x;
    const int wid = tid >> 5, lane = tid & 31;
    const int grp = lane >> 2, tig = lane & 3;
    const int m_base = (wid >> 2) * 64;   // 2 warp-rows of 64
    const int n_base = (wid & 3) * 32;    // 4 warp-cols of 32

    float acc[4][4][4];
#pragma unroll
    for (int mt = 0; mt < 4; mt++)
#pragma unroll
        for (int nt = 0; nt < 4; nt++)
#pragma unroll
            for (int i = 0; i < 4; i++) acc[mt][nt][i] = 0.f;

    const int r0 = tid >> 2;         // 0..63
    const int q0 = (tid & 3) * 4;    // k offset in floats: 0,4,8,12
    const int p0 = (tid & 3) * 2;    // pair index: 0,2,4,6
    const float* Ap = A + (size_t)r0 * lda + q0;
    const float* Bp = B + (size_t)r0 * ldb + q0;

    float4 ra0 = *(const float4*)(Ap);
    float4 ra1 = *(const float4*)(Ap + (size_t)64 * lda);
    float4 rb0 = *(const float4*)(Bp);
    float4 rb1 = *(const float4*)(Bp + (size_t)64 * ldb);

    const int T = K >> 4;
    for (int kb = 0; kb < T; kb++) {
        __syncthreads();
        {
            uint32_t h, l;
            split2(ra0.x, ra0.y, h, l); AsH[r0*LDW + p0]     = h; AsL[r0*LDW + p0]     = l;
            split2(ra0.z, ra0.w, h, l); AsH[r0*LDW + p0 + 1] = h; AsL[r0*LDW + p0 + 1] = l;
            split2(ra1.x, ra1.y, h, l); AsH[(r0+64)*LDW + p0]     = h; AsL[(r0+64)*LDW + p0]     = l;
            split2(ra1.z, ra1.w, h, l); AsH[(r0+64)*LDW + p0 + 1] = h; AsL[(r0+64)*LDW + p0 + 1] = l;
            split2(rb0.x, rb0.y, h, l); BsH[r0*LDW + p0]     = h; BsL[r0*LDW + p0]     = l;
            split2(rb0.z, rb0.w, h, l); BsH[r0*LDW + p0 + 1] = h; BsL[r0*LDW + p0 + 1] = l;
            split2(rb1.x, rb1.y, h, l); BsH[(r0+64)*LDW + p0]     = h; BsL[(r0+64)*LDW + p0]     = l;
            split2(rb1.z, rb1.w, h, l); BsH[(r0+64)*LDW + p0 + 1] = h; BsL[(r0+64)*LDW + p0 + 1] = l;
        }
        __syncthreads();
        if (kb + 1 < T) {
            int k0 = (kb + 1) << 4;
            ra0 = *(const float4*)(Ap + k0);
            ra1 = *(const float4*)(Ap + (size_t)64 * lda + k0);
            rb0 = *(const float4*)(Bp + k0);
            rb1 = *(const float4*)(Bp + (size_t)64 * ldb + k0);
        }

        uint32_t bH[4][2], bL[4][2];
#pragma unroll
        for (int nt = 0; nt < 4; nt++) {
            int col = n_base + nt*8 + grp;
            bH[nt][0] = BsH[col*LDW + tig];
            bH[nt][1] = BsH[col*LDW + tig + 4];
            bL[nt][0] = BsL[col*LDW + tig];
            bL[nt][1] = BsL[col*LDW + tig + 4];
        }
#pragma unroll
        for (int mt = 0; mt < 4; mt++) {
            int row  = m_base + mt*16 + grp;
            int row8 = row + 8;
            uint32_t aH[4], aL[4];
            aH[0] = AsH[row *LDW + tig];     aH[1] = AsH[row8*LDW + tig];
            aH[2] = AsH[row *LDW + tig + 4]; aH[3] = AsH[row8*LDW + tig + 4];
            aL[0] = AsL[row *LDW + tig];     aL[1] = AsL[row8*LDW + tig];
            aL[2] = AsL[row *LDW + tig + 4]; aL[3] = AsL[row8*LDW + tig + 4];
#pragma unroll
            for (int nt = 0; nt < 4; nt++) {
                mma_bf16(acc[mt][nt], aH, bH[nt]);
                mma_bf16(acc[mt][nt], aH, bL[nt]);
                mma_bf16(acc[mt][nt], aL, bH[nt]);
            }
        }
    }

    // epilogue: lane (grp,tig) owns rows (row,row+8), cols (col,col+1)
#pragma unroll
    for (int mt = 0; mt < 4; mt++) {
        int row = m_base + mt*16 + grp;
#pragma unroll
        for (int nt = 0; nt < 4; nt++) {
            int col = n_base + nt*8 + tig*2;
            float v0 = acc[mt][nt][0], v1 = acc[mt][nt][1];
            float v2 = acc[mt][nt][2], v3 = acc[mt][nt][3];
            if (bias) {
                float b0 = bias[col], b1 = bias[col+1];
                v0 += b0; v1 += b1; v2 += b0; v3 += b1;
            }
            if (relu) {
                v0 = fmaxf(v0, 0.f); v1 = fmaxf(v1, 0.f);
                v2 = fmaxf(v2, 0.f); v3 = fmaxf(v3, 0.f);
            }
            if (row < Mvalid) {
                float2 p; p.x = v0; p.y = v1;
                *(float2*)(C + (size_t)row * ldc + col) = p;
            }
            if (row + 8 < Mvalid) {
                float2 p; p.x = v2; p.y = v3;
                *(float2*)(C + (size_t)(row+8) * ldc + col) = p;
            }
        }
    }
}

// ---------------- GEMM wrappers ----------------
__global__ void __launch_bounds__(256, 2) k_gemm_qkv(const float* __restrict__ x)
{
    int n0 = blockIdx.x * 128, m0 = blockIdx.y * 128;
    gemm_mma_body(x + (size_t)m0 * DMODEL, DMODEL,
                  g_wqkvt + (size_t)n0 * DMODEL, DMODEL,
                  g_qkvtmp + (size_t)m0 * QKVN + n0, QKVN,
                  DMODEL, 128, nullptr, false);
}
__global__ void __launch_bounds__(256, 2) k_gemm_up(const float* __restrict__ b1)
{
    int e = blockIdx.z;
    int cnt = g_count[e];
    int m0 = blockIdx.y * 128;
    if (m0 >= cnt) return;
    int base = g_offset[e] + m0;
    int n0 = blockIdx.x * 128;
    int vr = cnt - m0; if (vr > 128) vr = 128;
    gemm_mma_body(g_xg + (size_t)base * DMODEL, DMODEL,
                  g_w1t + (size_t)e * FFDIM * DMODEL + (size_t)n0 * DMODEL, DMODEL,
                  g_hbuf + (size_t)base * FFDIM + n0, FFDIM,
                  DMODEL, vr, b1 + (size_t)e * FFDIM + n0, true);
}
__global__ void __launch_bounds__(256, 2) k_gemm_down(const float* __restrict__ b2)
{
    int e = blockIdx.z;
    int cnt = g_count[e];
    int m0 = blockIdx.y * 128;
    if (m0 >= cnt) return;
    int base = g_offset[e] + m0;
    int n0 = blockIdx.x * 128;
    int vr = cnt - m0; if (vr > 128) vr = 128;
    gemm_mma_body(g_hbuf + (size_t)base * FFDIM, FFDIM,
                  g_w2t + (size_t)e * DMODEL * FFDIM + (size_t)n0 * FFDIM, FFDIM,
                  g_eo + (size_t)base * DMODEL + n0, DMODEL,
                  FFDIM, vr, b2 + (size_t)e * DMODEL + n0, false);
}

// ---------------- transpose: in[e][r][c] -> out[e][c][r] ----------------
__global__ void k_transpose(const float* __restrict__ in, float* __restrict__ out,
                            int R, int C)
{
    __shared__ float t[32][33];
    size_t eo = (size_t)blockIdx.z * R * C;
    const float* I = in + eo;
    float* O = out + eo;
    int c0 = blockIdx.x * 32, r0 = blockIdx.y * 32;
    int tx = threadIdx.x, ty = threadIdx.y;
#pragma unroll
    for (int i = 0; i < 4; i++)
        t[ty + 8 * i][tx] = I[(size_t)(r0 + ty + 8 * i) * C + c0 + tx];
    __syncthreads();
#pragma unroll
    for (int i = 0; i < 4; i++)
        O[(size_t)(c0 + ty + 8 * i) * R + r0 + tx] = t[tx][ty + 8 * i];
}

// ---------------- K2: causal flash attention, Br=64, Bc=32, 128 threads ----------------
__global__ void k_attn()
{
    int qt = blockIdx.x;
    int bh = blockIdx.y;
    int b = bh >> 4, h = bh & 15;
    const float* Qp = g_qkvtmp + ((size_t)b * TLEN + qt * 64) * QKVN + h * 64;
    const float* Kp = g_qkvtmp + (size_t)b * TLEN * QKVN + DMODEL + h * 64;
    const float* Vp = g_qkvtmp + (size_t)b * TLEN * QKVN + 2 * DMODEL + h * 64;

    __shared__ float Qs[64][68];
    __shared__ float Ks[32][68];
    __shared__ float Vs[32][68];
    __shared__ float Ps[64][36];

    const int tid  = threadIdx.x;
    const int r    = tid >> 1;
    const int half = tid & 1;
    const int c0   = half * 16;
    const int d0   = half * 32;
    const float scale = 0.03125f;

    {
        int lr = tid >> 1, lc = (tid & 1) * 32;
#pragma unroll
        for (int i = 0; i < 8; i++)
            *(float4*)&Qs[lr][lc + i*4] = *(const float4*)(Qp + (size_t)lr*QKVN + lc + i*4);
    }

    float m_i = -1e30f, l_i = 0.f;
    float o[32];
#pragma unroll
    for (int d = 0; d < 32; d++) o[d] = 0.f;

    const int q_glob = qt*64 + r;
    const int nkt = 2*qt + 2;
    for (int kt = 0; kt < nkt; kt++) {
        __syncthreads();
        {
            int lr = tid >> 2, lc = (tid & 3) * 16;
#pragma unroll
            for (int i = 0; i < 4; i++) {
                *(float4*)&Ks[lr][lc + i*4] = *(const float4*)(Kp + ((size_t)kt*32 + lr)*QKVN + lc + i*4);
                *(float4*)&Vs[lr][lc + i*4] = *(const float4*)(Vp + ((size_t)kt*32 + lr)*QKVN + lc + i*4);
            }
        }
        __syncthreads();

        float s[16];
#pragma unroll
        for (int c = 0; c < 16; c++) s[c] = 0.f;
        for (int kk = 0; kk < 64; kk++) {
            float qv = Qs[r][kk];
#pragma unroll
            for (int c = 0; c < 16; c++) s[c] += qv * Ks[c0 + c][kk];
        }
        float mloc = -1e30f;
#pragma unroll
        for (int c = 0; c < 16; c++) {
            s[c] *= scale;
            int s_glob = kt*32 + c0 + c;
            if (s_glob > q_glob) s[c] = -1e30f;
            mloc = fmaxf(mloc, s[c]);
        }
        float mpair = fmaxf(mloc, __shfl_xor_sync(0xffffffffu, mloc, 1));
        float mnew  = fmaxf(m_i, mpair);
        float corr  = __expf(m_i - mnew);
        float lsum  = 0.f;
#pragma unroll
        for (int c = 0; c < 16; c++) {
            float p = __expf(s[c] - mnew);
            Ps[r][c0 + c] = p;
            lsum += p;
        }
        lsum += __shfl_xor_sync(0xffffffffu, lsum, 1);
        l_i = l_i * corr + lsum;
#pragma unroll
        for (int d = 0; d < 32; d++) o[d] *= corr;
        m_i = mnew;
        __syncthreads();
        for (int cc = 0; cc < 32; cc++) {
            float p = Ps[r][cc];
#pragma unroll
            for (int d = 0; d < 32; d++) o[d] += p * Vs[cc][d0 + d];
        }
    }
    float inv = 1.f / l_i;
    float* outp = g_attn + ((size_t)b*TLEN + q_glob)*DMODEL + h*64 + d0;
#pragma unroll
    for (int d = 0; d < 32; d++) outp[d] = o[d] * inv;
}

// ---------------- block reduce ----------------
__device__ __forceinline__ float block_sum(float v)
{
    __shared__ float red[256];
    int tid = threadIdx.x;
    red[tid] = v;
    __syncthreads();
    for (int s = 128; s > 0; s >>= 1) {
        if (tid < s) red[tid] += red[tid + s];
        __syncthreads();
    }
    float r = red[0];
    __syncthreads();
    return r;
}

// ---------------- K3: y = x + LN(attn) ----------------
__global__ void k_ln1(const float* __restrict__ x,
                      const float* __restrict__ g, const float* __restrict__ bln)
{
    int n = blockIdx.x;
    int tid = threadIdx.x;
    float v[4];
#pragma unroll
    for (int i = 0; i < 4; i++) v[i] = g_attn[(size_t)n*DMODEL + tid + i*256];
    float s = v[0] + v[1] + v[2] + v[3];
    s = block_sum(s);
    float mean = s * (1.f/DMODEL);
    float q = 0.f;
#pragma unroll
    for (int i = 0; i < 4; i++) { float dd = v[i] - mean; q += dd*dd; }
    q = block_sum(q);
    float rstd = rsqrtf(q * (1.f/DMODEL) + 1e-5f);
#pragma unroll
    for (int i = 0; i < 4; i++) {
        int d = tid + i*256;
        float ln = (v[i] - mean) * rstd * g[d] + bln[d];
        g_y[(size_t)n*DMODEL + d] = x[(size_t)n*DMODEL + d] + ln;
    }
}

// ---------------- K0: zero routing state ----------------
__global__ void k_zero()
{
    int i = threadIdx.x;
    if (i < NEXP) { g_count[i] = 0; g_cursor[i] = 0; }
}

// ---------------- K4: gate ----------------
__global__ void k_gate(const float* __restrict__ gate_W)
{
    int n = blockIdx.x*8 + (threadIdx.x >> 5);
    int lane = threadIdx.x & 31;
    const float* yr = g_y + (size_t)n*DMODEL;
    float acc[NEXP];
#pragma unroll
    for (int e = 0; e < NEXP; e++) acc[e] = 0.f;
    for (int d = lane; d < DMODEL; d += 32) {
        float yv = yr[d];
        const float* gw = gate_W + (size_t)d*NEXP;
#pragma unroll
        for (int e = 0; e < NEXP; e++) acc[e] += yv * gw[e];
    }
#pragma unroll
    for (int e = 0; e < NEXP; e++)
        for (int off = 16; off; off >>= 1)
            acc[e] += __shfl_xor_sync(0xffffffffu, acc[e], off);
    if (lane == 0) {
        float best = -1e30f; int bi = 0;
#pragma unroll
        for (int e = 0; e < NEXP; e++) if (acc[e] > best) { best = acc[e]; bi = e; }
        float best2 = -1e30f; int bi2 = 0;
#pragma unroll
        for (int e = 0; e < NEXP; e++) if (e != bi && acc[e] > best2) { best2 = acc[e]; bi2 = e; }
        float w0 = 1.f / (1.f + expf(best2 - best));
        g_topw[2*n]   = w0;  g_topw[2*n+1] = 1.f - w0;
        g_topi[2*n]   = bi;  g_topi[2*n+1] = bi2;
        atomicAdd(&g_count[bi],  1);
        atomicAdd(&g_count[bi2], 1);
    }
}

// ---------------- K5: offsets ----------------
__global__ void k_offs()
{
    if (threadIdx.x == 0) {
        int o = 0;
        for (int e = 0; e < NEXP; e++) { g_offset[e] = o; o += g_count[e]; }
    }
}

// ---------------- K6: gather ----------------
__global__ void k_gather()
{
    int p = blockIdx.x;
    int n = p >> 1;
    __shared__ int spos;
    if (threadIdx.x == 0) {
        int e = g_topi[p];
        int pos = g_offset[e] + atomicAdd(&g_cursor[e], 1);
        g_rowpos[p] = pos;
        spos = pos;
    }
    __syncthreads();
    int pos = spos;
    const float4* src = (const float4*)(g_y  + (size_t)n  *DMODEL);
    float4*       dst = (float4*)      (g_xg + (size_t)pos*DMODEL);
    dst[threadIdx.x] = src[threadIdx.x];
}

// ---------------- K9: combine + LN2 + residual ----------------
__global__ void k_out(const float* __restrict__ g, const float* __restrict__ bln,
                      float* __restrict__ out)
{
    int n = blockIdx.x;
    int tid = threadIdx.x;
    int r0 = g_rowpos[2*n], r1 = g_rowpos[2*n+1];
    float w0 = g_topw[2*n], w1 = g_topw[2*n+1];
    float v[4];
#pragma unroll
    for (int i = 0; i < 4; i++) {
        int d = tid + i*256;
        v[i] = w0 * g_eo[(size_t)r0*DMODEL + d] + w1 * g_eo[(size_t)r1*DMODEL + d];
    }
    float s = v[0] + v[1] + v[2] + v[3];
    s = block_sum(s);
    float mean = s * (1.f/DMODEL);
    float q = 0.f;
#pragma unroll
    for (int i = 0; i < 4; i++) { float dd = v[i] - mean; q += dd*dd; }
    q = block_sum(q);
    float rstd = rsqrtf(q * (1.f/DMODEL) + 1e-5f);
#pragma unroll
    for (int i = 0; i < 4; i++) {
        int d = tid + i*256;
        float ln = (v[i] - mean) * rstd * g[d] + bln[d];
        out[(size_t)n*DMODEL + d] = g_y[(size_t)n*DMODEL + d] + ln;
    }
}

// ---------------- launch ----------------
extern "C" void kernel_launch(void* const* d_in, const int* in_sizes, int n_in,
                              void* d_out, int out_size)
{
    const float* x      = (const float*)d_in[0];
    const float* Wq     = (const float*)d_in[1];
    const float* Wk     = (const float*)d_in[2];
    const float* Wv     = (const float*)d_in[3];
    const float* gate_W = (const float*)d_in[4];
    const float* W1     = (const float*)d_in[5];
    const float* b1     = (const float*)d_in[6];
    const float* W2     = (const float*)d_in[7];
    const float* b2     = (const float*)d_in[8];
    const float* ln1g   = (const float*)d_in[9];
    const float* ln1b   = (const float*)d_in[10];
    const float* ln2g   = (const float*)d_in[11];
    const float* ln2b   = (const float*)d_in[12];
    float* out = (float*)d_out;

    float *p_wqkvt = nullptr, *p_w1t = nullptr, *p_w2t = nullptr;
    cudaGetSymbolAddress((void**)&p_wqkvt, g_wqkvt);
    cudaGetSymbolAddress((void**)&p_w1t,   g_w1t);
    cudaGetSymbolAddress((void**)&p_w2t,   g_w2t);

    dim3 tb(32, 8);

    k_zero<<<1, 32>>>();
    // weight transposes (K-major B for mma.sync)
    k_transpose<<<dim3(2, 32, 16), tb>>>(Wq, p_wqkvt,                           DMODEL, HS);
    k_transpose<<<dim3(2, 32, 16), tb>>>(Wk, p_wqkvt + (size_t)DMODEL*DMODEL,   DMODEL, HS);
    k_transpose<<<dim3(2, 32, 16), tb>>>(Wv, p_wqkvt + (size_t)2*DMODEL*DMODEL, DMODEL, HS);
    k_transpose<<<dim3(FFDIM/32, DMODEL/32, NEXP), tb>>>(W1, p_w1t, DMODEL, FFDIM);
    k_transpose<<<dim3(DMODEL/32, FFDIM/32, NEXP), tb>>>(W2, p_w2t, FFDIM, DMODEL);

    k_gemm_qkv<<<dim3(QKVN/128, NTOK/128), 256>>>(x);
    k_attn    <<<dim3(TLEN/64, BATCH*NHEAD), 128>>>();
    k_ln1     <<<NTOK, 256>>>(x, ln1g, ln1b);
    k_gate    <<<NTOK/8, 256>>>(gate_W);
    k_offs    <<<1, 1>>>();
    k_gather  <<<NTOK*2, 256>>>();
    k_gemm_up  <<<dim3(FFDIM/128, NTOK/128, NEXP), 256>>>(b1);
    k_gemm_down<<<dim3(DMODEL/128, NTOK/128, NEXP), 256>>>(b2);
    k_out     <<<NTOK, 256>>>(ln2g, ln2b, out);
}

// round 5
// speedup vs baseline: 2.3591x; 1.0917x over previous
#include <cuda_runtime.h>
#include <cuda_bf16.h>
#include <math.h>
#include <stdint.h>

#define DMODEL 1024
#define TLEN   1024
#define BATCH  2
#define NHEAD  16
#define HS     64
#define NEXP   8
#define FFDIM  4096
#define NTOK   (BATCH*TLEN)          // 2048
#define QKVN   (3*DMODEL)            // 3072
#define GROWS  (2*NTOK + 192)        // gathered rows capacity (+pad for tile overread)

// ---------------- scratch (__device__ globals; no allocs) ----------------
// pre-split packed bf16x2 weights, K-major [N][K/2] u32 (lo16 = even k)
__device__ uint32_t g_wqkvh[(size_t)QKVN*DMODEL/2];
__device__ uint32_t g_wqkvl[(size_t)QKVN*DMODEL/2];
__device__ uint32_t g_w1h[(size_t)NEXP*FFDIM*DMODEL/2];
__device__ uint32_t g_w1l[(size_t)NEXP*FFDIM*DMODEL/2];
__device__ uint32_t g_w2h[(size_t)NEXP*DMODEL*FFDIM/2];
__device__ uint32_t g_w2l[(size_t)NEXP*DMODEL*FFDIM/2];

__device__ float g_qkvtmp[(size_t)NTOK*QKVN];           // [2048,3072]
__device__ float g_attn[(size_t)NTOK*DMODEL];           // [b,t,d] concat
__device__ float g_y[(size_t)NTOK*DMODEL];
__device__ float g_topw[NTOK*2];
__device__ int   g_topi[NTOK*2];
__device__ int   g_rowpos[NTOK*2];
__device__ int   g_count[NEXP];
__device__ int   g_offset[NEXP];
__device__ int   g_cursor[NEXP];
__device__ float g_xg[(size_t)GROWS*DMODEL];
__device__ float g_hbuf[(size_t)GROWS*FFDIM];
__device__ float g_eo[(size_t)GROWS*DMODEL];

// ================= bf16x3 split-precision mma helpers =================
__device__ __forceinline__ void mma_bf16(float d[4], const uint32_t a[4], const uint32_t b[2]) {
    asm volatile(
        "mma.sync.aligned.m16n8k16.row.col.f32.bf16.bf16.f32 "
        "{%0,%1,%2,%3}, {%4,%5,%6,%7}, {%8,%9}, {%0,%1,%2,%3};"
        : "+f"(d[0]), "+f"(d[1]), "+f"(d[2]), "+f"(d[3])
        : "r"(a[0]), "r"(a[1]), "r"(a[2]), "r"(a[3]), "r"(b[0]), "r"(b[1]));
}
// split (x,y) into packed bf16x2 hi and lo words; x -> low 16 bits (even k)
__device__ __forceinline__ void split2(float x, float y, uint32_t& h, uint32_t& l) {
    unsigned short hx = __bfloat16_as_ushort(__float2bfloat16_rn(x));
    unsigned short hy = __bfloat16_as_ushort(__float2bfloat16_rn(y));
    float fx = __uint_as_float(((uint32_t)hx) << 16);
    float fy = __uint_as_float(((uint32_t)hy) << 16);
    unsigned short lx = __bfloat16_as_ushort(__float2bfloat16_rn(x - fx));
    unsigned short ly = __bfloat16_as_ushort(__float2bfloat16_rn(y - fy));
    h = ((uint32_t)hy << 16) | (uint32_t)hx;
    l = ((uint32_t)ly << 16) | (uint32_t)lx;
}

// ================= bf16x3 GEMM body: 128x128 tile, Kchunk=16, 256 thr =================
// A: fp32 [M][lda], split in-kernel. B: pre-split packed [N][ldbw] u32 (hi/lo).
#define LDW 12   // u32 words per row (8 used + 4 pad)

__device__ __forceinline__ void gemm_mma_body(
    const float* __restrict__ A, int lda,
    const uint32_t* __restrict__ BH, const uint32_t* __restrict__ BL, int ldbw,
    float* __restrict__ C, int ldc,
    int K, int Mvalid, const float* __restrict__ bias, bool relu)
{
    __shared__ uint32_t AsH[128*LDW];
    __shared__ uint32_t AsL[128*LDW];
    __shared__ uint32_t BsH[128*LDW];
    __shared__ uint32_t BsL[128*LDW];

    const int tid = threadIdx.x;
    const int wid = tid >> 5, lane = tid & 31;
    const int grp = lane >> 2, tig = lane & 3;
    const int m_base = (wid >> 2) * 64;   // 2 warp-rows of 64
    const int n_base = (wid & 3) * 32;    // 4 warp-cols of 32

    float acc[4][4][4];
#pragma unroll
    for (int mt = 0; mt < 4; mt++)
#pragma unroll
        for (int nt = 0; nt < 4; nt++)
#pragma unroll
            for (int i = 0; i < 4; i++) acc[mt][nt][i] = 0.f;

    // A loader mapping
    const int r0 = tid >> 2;         // 0..63 (rows r0 and r0+64)
    const int q0 = (tid & 3) * 4;    // k offset in floats
    const int p0 = (tid & 3) * 2;    // word pair index
    const float* Ap = A + (size_t)r0 * lda + q0;
    // B loader mapping: row 0..127, half 0/1 -> words 0..3 / 4..7
    const int br = tid >> 1;
    const int hh = tid & 1;
    const size_t Bpw = (size_t)br * ldbw + hh * 4;

    float4 ra0 = *(const float4*)(Ap);
    float4 ra1 = *(const float4*)(Ap + (size_t)64 * lda);
    uint4 rbh = *(const uint4*)(BH + Bpw);
    uint4 rbl = *(const uint4*)(BL + Bpw);

    const int T = K >> 4;
    for (int kb = 0; kb < T; kb++) {
        __syncthreads();
        {
            uint32_t h, l;
            split2(ra0.x, ra0.y, h, l); AsH[r0*LDW + p0]     = h; AsL[r0*LDW + p0]     = l;
            split2(ra0.z, ra0.w, h, l); AsH[r0*LDW + p0 + 1] = h; AsL[r0*LDW + p0 + 1] = l;
            split2(ra1.x, ra1.y, h, l); AsH[(r0+64)*LDW + p0]     = h; AsL[(r0+64)*LDW + p0]     = l;
            split2(ra1.z, ra1.w, h, l); AsH[(r0+64)*LDW + p0 + 1] = h; AsL[(r0+64)*LDW + p0 + 1] = l;
            *(uint4*)&BsH[br*LDW + hh*4] = rbh;
            *(uint4*)&BsL[br*LDW + hh*4] = rbl;
        }
        __syncthreads();
        if (kb + 1 < T) {
            int k0 = (kb + 1) << 4;
            ra0 = *(const float4*)(Ap + k0);
            ra1 = *(const float4*)(Ap + (size_t)64 * lda + k0);
            rbh = *(const uint4*)(BH + Bpw + (size_t)(kb+1)*8);
            rbl = *(const uint4*)(BL + Bpw + (size_t)(kb+1)*8);
        }

        uint32_t bH[4][2], bL[4][2];
#pragma unroll
        for (int nt = 0; nt < 4; nt++) {
            int col = n_base + nt*8 + grp;
            bH[nt][0] = BsH[col*LDW + tig];
            bH[nt][1] = BsH[col*LDW + tig + 4];
            bL[nt][0] = BsL[col*LDW + tig];
            bL[nt][1] = BsL[col*LDW + tig + 4];
        }
#pragma unroll
        for (int mt = 0; mt < 4; mt++) {
            int row  = m_base + mt*16 + grp;
            int row8 = row + 8;
            uint32_t aH[4], aL[4];
            aH[0] = AsH[row *LDW + tig];     aH[1] = AsH[row8*LDW + tig];
            aH[2] = AsH[row *LDW + tig + 4]; aH[3] = AsH[row8*LDW + tig + 4];
            aL[0] = AsL[row *LDW + tig];     aL[1] = AsL[row8*LDW + tig];
            aL[2] = AsL[row *LDW + tig + 4]; aL[3] = AsL[row8*LDW + tig + 4];
#pragma unroll
            for (int nt = 0; nt < 4; nt++) {
                mma_bf16(acc[mt][nt], aH, bH[nt]);
                mma_bf16(acc[mt][nt], aH, bL[nt]);
                mma_bf16(acc[mt][nt], aL, bH[nt]);
            }
        }
    }

    // epilogue
#pragma unroll
    for (int mt = 0; mt < 4; mt++) {
        int row = m_base + mt*16 + grp;
#pragma unroll
        for (int nt = 0; nt < 4; nt++) {
            int col = n_base + nt*8 + tig*2;
            float v0 = acc[mt][nt][0], v1 = acc[mt][nt][1];
            float v2 = acc[mt][nt][2], v3 = acc[mt][nt][3];
            if (bias) {
                float b0 = bias[col], b1 = bias[col+1];
                v0 += b0; v1 += b1; v2 += b0; v3 += b1;
            }
            if (relu) {
                v0 = fmaxf(v0, 0.f); v1 = fmaxf(v1, 0.f);
                v2 = fmaxf(v2, 0.f); v3 = fmaxf(v3, 0.f);
            }
            if (row < Mvalid) {
                float2 p; p.x = v0; p.y = v1;
                *(float2*)(C + (size_t)row * ldc + col) = p;
            }
            if (row + 8 < Mvalid) {
                float2 p; p.x = v2; p.y = v3;
                *(float2*)(C + (size_t)(row+8) * ldc + col) = p;
            }
        }
    }
}

// ---------------- GEMM wrappers ----------------
__global__ void __launch_bounds__(256, 2) k_gemm_qkv(const float* __restrict__ x)
{
    int n0 = blockIdx.x * 128, m0 = blockIdx.y * 128;
    gemm_mma_body(x + (size_t)m0 * DMODEL, DMODEL,
                  g_wqkvh + (size_t)n0 * (DMODEL/2), g_wqkvl + (size_t)n0 * (DMODEL/2), DMODEL/2,
                  g_qkvtmp + (size_t)m0 * QKVN + n0, QKVN,
                  DMODEL, 128, nullptr, false);
}
__global__ void __launch_bounds__(256, 2) k_gemm_up(const float* __restrict__ b1)
{
    int e = blockIdx.z;
    int cnt = g_count[e];
    int m0 = blockIdx.y * 128;
    if (m0 >= cnt) return;
    int base = g_offset[e] + m0;
    int n0 = blockIdx.x * 128;
    int vr = cnt - m0; if (vr > 128) vr = 128;
    const size_t wb = (size_t)e * FFDIM * (DMODEL/2) + (size_t)n0 * (DMODEL/2);
    gemm_mma_body(g_xg + (size_t)base * DMODEL, DMODEL,
                  g_w1h + wb, g_w1l + wb, DMODEL/2,
                  g_hbuf + (size_t)base * FFDIM + n0, FFDIM,
                  DMODEL, vr, b1 + (size_t)e * FFDIM + n0, true);
}
__global__ void __launch_bounds__(256, 2) k_gemm_down(const float* __restrict__ b2)
{
    int e = blockIdx.z;
    int cnt = g_count[e];
    int m0 = blockIdx.y * 128;
    if (m0 >= cnt) return;
    int base = g_offset[e] + m0;
    int n0 = blockIdx.x * 128;
    int vr = cnt - m0; if (vr > 128) vr = 128;
    const size_t wb = (size_t)e * DMODEL * (FFDIM/2) + (size_t)n0 * (FFDIM/2);
    gemm_mma_body(g_hbuf + (size_t)base * FFDIM, FFDIM,
                  g_w2h + wb, g_w2l + wb, FFDIM/2,
                  g_eo + (size_t)base * DMODEL + n0, DMODEL,
                  FFDIM, vr, b2 + (size_t)e * DMODEL + n0, false);
}

// ---------------- transpose + bf16 split: in[z][R][C] fp32 -> out[z][C][R/2] packed u32 ----------------
__global__ void k_tsplit(const float* __restrict__ in,
                         uint32_t* __restrict__ outH, uint32_t* __restrict__ outL,
                         int R, int C)
{
    __shared__ float t[32][33];
    in   += (size_t)blockIdx.z * R * C;
    outH += (size_t)blockIdx.z * C * (R/2);
    outL += (size_t)blockIdx.z * C * (R/2);
    int c0 = blockIdx.x * 32, r0 = blockIdx.y * 32;
    int tid = threadIdx.x;
    int lr = tid >> 5, tx = tid & 31;
#pragma unroll
    for (int i = 0; i < 4; i++)
        t[lr + 8*i][tx] = in[(size_t)(r0 + lr + 8*i) * C + c0 + tx];
    __syncthreads();
#pragma unroll
    for (int rep = 0; rep < 2; rep++) {
        int w = tid + rep*256;
        int c = w >> 4, rp = w & 15;
        uint32_t h, l;
        split2(t[2*rp][c], t[2*rp+1][c], h, l);
        size_t o = (size_t)(c0 + c) * (R/2) + (r0 >> 1) + rp;
        outH[o] = h; outL[o] = l;
    }
}

// ---------------- K2: causal flash attention, Br=64, Bc=32, 128 thr, 4x4 reg tiles ----------------
__global__ void k_attn()
{
    int qt = blockIdx.x;
    int bh = blockIdx.y;
    int b = bh >> 4, h = bh & 15;
    const float* Qp = g_qkvtmp + ((size_t)b * TLEN + qt * 64) * QKVN + h * 64;
    const float* Kp = g_qkvtmp + (size_t)b * TLEN * QKVN + DMODEL + h * 64;
    const float* Vp = g_qkvtmp + (size_t)b * TLEN * QKVN + 2 * DMODEL + h * 64;

    __shared__ float Qs[64][65];
    __shared__ float Ks[32][65];
    __shared__ float Vs[32][68];
    __shared__ float Ps[64][36];

    const int tid = threadIdx.x;          // 128
    const int ty = tid >> 3, tx = tid & 7;
    const int r0 = ty * 4;                // 4 query rows
    const int c0 = tx * 4;                // 4 score cols
    const int d0 = tx * 8;                // 8 output dims
    const float scale = 0.03125f;         // 1024^-0.5

    { // load Q tile (scalar stores; pad 65)
        int lr = tid >> 1, lc = (tid & 1) * 32;
#pragma unroll
        for (int i = 0; i < 8; i++) {
            float4 v = *(const float4*)(Qp + (size_t)lr * QKVN + lc + i*4);
            Qs[lr][lc+i*4+0] = v.x; Qs[lr][lc+i*4+1] = v.y;
            Qs[lr][lc+i*4+2] = v.z; Qs[lr][lc+i*4+3] = v.w;
        }
    }

    float m_i[4], l_i[4], o[4][8];
#pragma unroll
    for (int i = 0; i < 4; i++) {
        m_i[i] = -1e30f; l_i[i] = 0.f;
#pragma unroll
        for (int d = 0; d < 8; d++) o[i][d] = 0.f;
    }

    const int nkt = 2*qt + 2;
    for (int kt = 0; kt < nkt; kt++) {
        __syncthreads();
        {
            int lr = tid >> 2, lc = (tid & 3) * 16;
#pragma unroll
            for (int i = 0; i < 4; i++) {
                float4 kv = *(const float4*)(Kp + ((size_t)kt*32 + lr) * QKVN + lc + i*4);
                Ks[lr][lc+i*4+0] = kv.x; Ks[lr][lc+i*4+1] = kv.y;
                Ks[lr][lc+i*4+2] = kv.z; Ks[lr][lc+i*4+3] = kv.w;
                *(float4*)&Vs[lr][lc + i*4] =
                    *(const float4*)(Vp + ((size_t)kt*32 + lr) * QKVN + lc + i*4);
            }
        }
        __syncthreads();

        // QK: 4x4 register tile
        float s[4][4];
#pragma unroll
        for (int i = 0; i < 4; i++)
#pragma unroll
            for (int j = 0; j < 4; j++) s[i][j] = 0.f;
        for (int kk = 0; kk < 64; kk++) {
            float qv[4], kv[4];
#pragma unroll
            for (int i = 0; i < 4; i++) qv[i] = Qs[r0+i][kk];
#pragma unroll
            for (int j = 0; j < 4; j++) kv[j] = Ks[c0+j][kk];
#pragma unroll
            for (int i = 0; i < 4; i++)
#pragma unroll
                for (int j = 0; j < 4; j++) s[i][j] += qv[i] * kv[j];
        }

        // mask + online softmax (row reductions across tx = lane bits 0..2)
        float corr[4];
#pragma unroll
        for (int i = 0; i < 4; i++) {
            int rg = qt*64 + r0 + i;
            float mloc = -1e30f;
#pragma unroll
            for (int j = 0; j < 4; j++) {
                int cg = kt*32 + c0 + j;
                s[i][j] = (cg <= rg) ? s[i][j] * scale : -1e30f;
                mloc = fmaxf(mloc, s[i][j]);
            }
            mloc = fmaxf(mloc, __shfl_xor_sync(0xffffffffu, mloc, 1));
            mloc = fmaxf(mloc, __shfl_xor_sync(0xffffffffu, mloc, 2));
            mloc = fmaxf(mloc, __shfl_xor_sync(0xffffffffu, mloc, 4));
            float mnew = fmaxf(m_i[i], mloc);
            corr[i] = __expf(m_i[i] - mnew);
            float ls = 0.f;
#pragma unroll
            for (int j = 0; j < 4; j++) {
                float p = __expf(s[i][j] - mnew);
                Ps[r0+i][c0+j] = p;
                ls += p;
            }
            ls += __shfl_xor_sync(0xffffffffu, ls, 1);
            ls += __shfl_xor_sync(0xffffffffu, ls, 2);
            ls += __shfl_xor_sync(0xffffffffu, ls, 4);
            l_i[i] = l_i[i] * corr[i] + ls;
            m_i[i] = mnew;
#pragma unroll
            for (int d = 0; d < 8; d++) o[i][d] *= corr[i];
        }
        __syncthreads();

        // PV: 4 rows x 8 dims, vectorized V reads
        for (int cc = 0; cc < 32; cc++) {
            float pv[4];
#pragma unroll
            for (int i = 0; i < 4; i++) pv[i] = Ps[r0+i][cc];
            float4 va = *(const float4*)&Vs[cc][d0];
            float4 vb = *(const float4*)&Vs[cc][d0+4];
#pragma unroll
            for (int i = 0; i < 4; i++) {
                o[i][0] += pv[i]*va.x; o[i][1] += pv[i]*va.y;
                o[i][2] += pv[i]*va.z; o[i][3] += pv[i]*va.w;
                o[i][4] += pv[i]*vb.x; o[i][5] += pv[i]*vb.y;
                o[i][6] += pv[i]*vb.z; o[i][7] += pv[i]*vb.w;
            }
        }
    }

#pragma unroll
    for (int i = 0; i < 4; i++) {
        float inv = 1.f / l_i[i];
        float* outp = g_attn + ((size_t)b*TLEN + qt*64 + r0 + i)*DMODEL + h*64 + d0;
        float4 w0, w1;
        w0.x = o[i][0]*inv; w0.y = o[i][1]*inv; w0.z = o[i][2]*inv; w0.w = o[i][3]*inv;
        w1.x = o[i][4]*inv; w1.y = o[i][5]*inv; w1.z = o[i][6]*inv; w1.w = o[i][7]*inv;
        *(float4*)(outp)     = w0;
        *(float4*)(outp + 4) = w1;
    }
}

// ---------------- block reduce ----------------
__device__ __forceinline__ float block_sum(float v)
{
    __shared__ float red[256];
    int tid = threadIdx.x;
    red[tid] = v;
    __syncthreads();
    for (int s = 128; s > 0; s >>= 1) {
        if (tid < s) red[tid] += red[tid + s];
        __syncthreads();
    }
    float r = red[0];
    __syncthreads();
    return r;
}

// ---------------- K3: y = x + LN(attn) ----------------
__global__ void k_ln1(const float* __restrict__ x,
                      const float* __restrict__ g, const float* __restrict__ bln)
{
    int n = blockIdx.x;
    int tid = threadIdx.x;
    float v[4];
#pragma unroll
    for (int i = 0; i < 4; i++) v[i] = g_attn[(size_t)n*DMODEL + tid + i*256];
    float s = v[0] + v[1] + v[2] + v[3];
    s = block_sum(s);
    float mean = s * (1.f/DMODEL);
    float q = 0.f;
#pragma unroll
    for (int i = 0; i < 4; i++) { float dd = v[i] - mean; q += dd*dd; }
    q = block_sum(q);
    float rstd = rsqrtf(q * (1.f/DMODEL) + 1e-5f);
#pragma unroll
    for (int i = 0; i < 4; i++) {
        int d = tid + i*256;
        float ln = (v[i] - mean) * rstd * g[d] + bln[d];
        g_y[(size_t)n*DMODEL + d] = x[(size_t)n*DMODEL + d] + ln;
    }
}

// ---------------- K0: zero routing state ----------------
__global__ void k_zero()
{
    int i = threadIdx.x;
    if (i < NEXP) { g_count[i] = 0; g_cursor[i] = 0; }
}

// ---------------- K4: gate ----------------
__global__ void k_gate(const float* __restrict__ gate_W)
{
    int n = blockIdx.x*8 + (threadIdx.x >> 5);
    int lane = threadIdx.x & 31;
    const float* yr = g_y + (size_t)n*DMODEL;
    float acc[NEXP];
#pragma unroll
    for (int e = 0; e < NEXP; e++) acc[e] = 0.f;
    for (int d = lane; d < DMODEL; d += 32) {
        float yv = yr[d];
        const float* gw = gate_W + (size_t)d*NEXP;
#pragma unroll
        for (int e = 0; e < NEXP; e++) acc[e] += yv * gw[e];
    }
#pragma unroll
    for (int e = 0; e < NEXP; e++)
        for (int off = 16; off; off >>= 1)
            acc[e] += __shfl_xor_sync(0xffffffffu, acc[e], off);
    if (lane == 0) {
        float best = -1e30f; int bi = 0;
#pragma unroll
        for (int e = 0; e < NEXP; e++) if (acc[e] > best) { best = acc[e]; bi = e; }
        float best2 = -1e30f; int bi2 = 0;
#pragma unroll
        for (int e = 0; e < NEXP; e++) if (e != bi && acc[e] > best2) { best2 = acc[e]; bi2 = e; }
        float w0 = 1.f / (1.f + expf(best2 - best));
        g_topw[2*n]   = w0;  g_topw[2*n+1] = 1.f - w0;
        g_topi[2*n]   = bi;  g_topi[2*n+1] = bi2;
        atomicAdd(&g_count[bi],  1);
        atomicAdd(&g_count[bi2], 1);
    }
}

// ---------------- K5: offsets ----------------
__global__ void k_offs()
{
    if (threadIdx.x == 0) {
        int o = 0;
        for (int e = 0; e < NEXP; e++) { g_offset[e] = o; o += g_count[e]; }
    }
}

// ---------------- K6: gather ----------------
__global__ void k_gather()
{
    int p = blockIdx.x;
    int n = p >> 1;
    __shared__ int spos;
    if (threadIdx.x == 0) {
        int e = g_topi[p];
        int pos = g_offset[e] + atomicAdd(&g_cursor[e], 1);
        g_rowpos[p] = pos;
        spos = pos;
    }
    __syncthreads();
    int pos = spos;
    const float4* src = (const float4*)(g_y  + (size_t)n  *DMODEL);
    float4*       dst = (float4*)      (g_xg + (size_t)pos*DMODEL);
    dst[threadIdx.x] = src[threadIdx.x];
}

// ---------------- K9: combine + LN2 + residual ----------------
__global__ void k_out(const float* __restrict__ g, const float* __restrict__ bln,
                      float* __restrict__ out)
{
    int n = blockIdx.x;
    int tid = threadIdx.x;
    int r0 = g_rowpos[2*n], r1 = g_rowpos[2*n+1];
    float w0 = g_topw[2*n], w1 = g_topw[2*n+1];
    float v[4];
#pragma unroll
    for (int i = 0; i < 4; i++) {
        int d = tid + i*256;
        v[i] = w0 * g_eo[(size_t)r0*DMODEL + d] + w1 * g_eo[(size_t)r1*DMODEL + d];
    }
    float s = v[0] + v[1] + v[2] + v[3];
    s = block_sum(s);
    float mean = s * (1.f/DMODEL);
    float q = 0.f;
#pragma unroll
    for (int i = 0; i < 4; i++) { float dd = v[i] - mean; q += dd*dd; }
    q = block_sum(q);
    float rstd = rsqrtf(q * (1.f/DMODEL) + 1e-5f);
#pragma unroll
    for (int i = 0; i < 4; i++) {
        int d = tid + i*256;
        float ln = (v[i] - mean) * rstd * g[d] + bln[d];
        out[(size_t)n*DMODEL + d] = g_y[(size_t)n*DMODEL + d] + ln;
    }
}

// ---------------- launch ----------------
extern "C" void kernel_launch(void* const* d_in, const int* in_sizes, int n_in,
                              void* d_out, int out_size)
{
    const float* x      = (const float*)d_in[0];
    const float* Wq     = (const float*)d_in[1];
    const float* Wk     = (const float*)d_in[2];
    const float* Wv     = (const float*)d_in[3];
    const float* gate_W = (const float*)d_in[4];
    const float* W1     = (const float*)d_in[5];
    const float* b1     = (const float*)d_in[6];
    const float* W2     = (const float*)d_in[7];
    const float* b2     = (const float*)d_in[8];
    const float* ln1g   = (const float*)d_in[9];
    const float* ln1b   = (const float*)d_in[10];
    const float* ln2g   = (const float*)d_in[11];
    const float* ln2b   = (const float*)d_in[12];
    float* out = (float*)d_out;

    uint32_t *p_wqkvh, *p_wqkvl, *p_w1h, *p_w1l, *p_w2h, *p_w2l;
    cudaGetSymbolAddress((void**)&p_wqkvh, g_wqkvh);
    cudaGetSymbolAddress((void**)&p_wqkvl, g_wqkvl);
    cudaGetSymbolAddress((void**)&p_w1h,   g_w1h);
    cudaGetSymbolAddress((void**)&p_w1l,   g_w1l);
    cudaGetSymbolAddress((void**)&p_w2h,   g_w2h);
    cudaGetSymbolAddress((void**)&p_w2l,   g_w2l);

    k_zero<<<1, 32>>>();
    // weight transpose + bf16 hi/lo split, K-major packed output
    k_tsplit<<<dim3(2, 32, 16), 256>>>(Wq, p_wqkvh,            p_wqkvl,            DMODEL, HS);
    k_tsplit<<<dim3(2, 32, 16), 256>>>(Wk, p_wqkvh + 1024*512, p_wqkvl + 1024*512, DMODEL, HS);
    k_tsplit<<<dim3(2, 32, 16), 256>>>(Wv, p_wqkvh + 2048*512, p_wqkvl + 2048*512, DMODEL, HS);
    k_tsplit<<<dim3(FFDIM/32, DMODEL/32, NEXP), 256>>>(W1, p_w1h, p_w1l, DMODEL, FFDIM);
    k_tsplit<<<dim3(DMODEL/32, FFDIM/32, NEXP), 256>>>(W2, p_w2h, p_w2l, FFDIM, DMODEL);

    k_gemm_qkv<<<dim3(QKVN/128, NTOK/128), 256>>>(x);
    k_attn    <<<dim3(TLEN/64, BATCH*NHEAD), 128>>>();
    k_ln1     <<<NTOK, 256>>>(x, ln1g, ln1b);
    k_gate    <<<NTOK/8, 256>>>(gate_W);
    k_offs    <<<1, 1>>>();
    k_gather  <<<NTOK*2, 256>>>();
    k_gemm_up  <<<dim3(FFDIM/128, NTOK/128, NEXP), 256>>>(b1);
    k_gemm_down<<<dim3(DMODEL/128, NTOK/128, NEXP), 256>>>(b2);
    k_out     <<<NTOK, 256>>>(ln2g, ln2b, out);
}